// round 5
// baseline (speedup 1.0000x reference)
#include <cuda_runtime.h>

#define NNODES 100000
#define NEDGES 600000
#define FIN 128
#define FOUT 64
#define NBLK 98   // ceil(NNODES/1024)

typedef unsigned long long ull;

// ---------------- scratch (static device allocations) ------------------------
__device__ float g_deg[NNODES];
__device__ float g_dis[NNODES];       // rsqrt(deg+1)
__device__ float g_invdeg[NNODES];    // 1/(deg+1)
__device__ float g_xp[(size_t)NNODES * FOUT];
__device__ float g_inv_sigma;
__device__ int   g_is64;
__device__ int   g_cnt[NNODES];       // in-degree counts
__device__ int   g_offloc[NNODES];    // block-local exclusive scan
__device__ int   g_off[NNODES + 1];   // CSR offsets
__device__ int   g_cur[NNODES];       // bucket cursors
__device__ int   g_bsum[NBLK];
__device__ int   g_bpre[NBLK];
__device__ int2  g_rc[NEDGES];        // decoded (row, col)
__device__ uint2 g_ed[NEDGES];        // sorted-by-col: {src, norm_e bits}

__device__ __forceinline__ int edge_at(const void* ei, long long i) {
    if (g_is64) return (int)((const long long*)ei)[i];
    return ((const int*)ei)[i];
}

__device__ __forceinline__ ull fma2(ull a, ull b, ull c) {
    ull d;
    asm("fma.rn.f32x2 %0, %1, %2, %3;" : "=l"(d) : "l"(a), "l"(b), "l"(c));
    return d;
}
__device__ __forceinline__ ull dup2(float x) {
    ull d;
    asm("mov.b64 %0, {%1, %1};" : "=l"(d) : "f"(x));
    return d;
}

// ---------------- kernel 0: dtype detect + spectral norm ---------------------
__global__ void k_prep(const void* ei, const float* __restrict__ W,
                       const float* __restrict__ u) {
    __shared__ float sv[64];
    __shared__ float red[128];
    int t = threadIdx.x;  // 128 threads

    if (t == 0) {
        const int* e32 = (const int*)ei;
        int is64 = 1;
        for (int i = 1; i < 256; i += 2)
            if (e32[i] != 0) { is64 = 0; break; }
        g_is64 = is64;
    }

    float vt = 0.f;
    if (t < 64) {
        #pragma unroll 8
        for (int i = 0; i < FIN; i++) vt += W[i * FOUT + t] * u[i];
    }
    red[t] = (t < 64) ? vt * vt : 0.f;
    __syncthreads();
    for (int s = 64; s > 0; s >>= 1) {
        if (t < s) red[t] += red[t + s];
        __syncthreads();
    }
    float nv = sqrtf(red[0]);
    __syncthreads();
    if (t < 64) sv[t] = vt / (nv + 1e-12f);
    __syncthreads();

    float wv = 0.f;
    #pragma unroll 8
    for (int j = 0; j < FOUT; j++) wv += W[t * FOUT + j] * sv[j];
    red[t] = wv * wv;
    __syncthreads();
    for (int s = 64; s > 0; s >>= 1) {
        if (t < s) red[t] += red[t + s];
        __syncthreads();
    }
    if (t == 0) {
        float s2 = red[0];
        float n = sqrtf(s2);
        float sigma = s2 / (n + 1e-12f);   // u2.(Wv) = ||Wv||^2/(||Wv||+eps)
        g_inv_sigma = 1.0f / sigma;
    }
}

// ---------------- kernel 1: zero deg + counts --------------------------------
__global__ void k_zero() {
    int i = blockIdx.x * blockDim.x + threadIdx.x;
    if (i < NNODES) { g_deg[i] = 0.f; g_cnt[i] = 0; }
}

// ---------------- kernel 2: degree + count + decode edges --------------------
__global__ void k_deg(const void* ei, const float* __restrict__ ew) {
    int e = blockIdx.x * blockDim.x + threadIdx.x;
    if (e >= NEDGES) return;
    int row = edge_at(ei, e);
    int col = edge_at(ei, (long long)NEDGES + e);
    g_rc[e] = make_int2(row, col);
    float w = 1.f / (1.f + __expf(-ew[e]));
    atomicAdd(&g_deg[col], w);
    atomicAdd(&g_cnt[col], 1);
}

// ---------------- kernel 3: dis / invdeg -------------------------------------
__global__ void k_dis() {
    int i = blockIdx.x * blockDim.x + threadIdx.x;
    if (i >= NNODES) return;
    float d = g_deg[i] + 1.f;
    g_dis[i] = rsqrtf(d);
    g_invdeg[i] = 1.f / d;
}

// ---------------- scan: block-local inclusive scan of counts -----------------
__global__ __launch_bounds__(1024) void k_scan_blk() {
    __shared__ int s[1024];
    int t = threadIdx.x;
    int i = blockIdx.x * 1024 + t;
    int v = (i < NNODES) ? g_cnt[i] : 0;
    s[t] = v;
    __syncthreads();
    #pragma unroll
    for (int off = 1; off < 1024; off <<= 1) {
        int tmp = (t >= off) ? s[t - off] : 0;
        __syncthreads();
        s[t] += tmp;
        __syncthreads();
    }
    if (i < NNODES) g_offloc[i] = s[t] - v;   // exclusive
    if (t == 1023) g_bsum[blockIdx.x] = s[1023];
}

// ---------------- scan: top-level scan of block sums -------------------------
__global__ void k_scan_top() {
    __shared__ int s[128];
    int t = threadIdx.x;
    int v = (t < NBLK) ? g_bsum[t] : 0;
    s[t] = v;
    __syncthreads();
    #pragma unroll
    for (int off = 1; off < 128; off <<= 1) {
        int tmp = (t >= off) ? s[t - off] : 0;
        __syncthreads();
        s[t] += tmp;
        __syncthreads();
    }
    if (t < NBLK) g_bpre[t] = s[t] - v;       // exclusive
}

// ---------------- scan: combine + init cursors -------------------------------
__global__ void k_scan_add() {
    int i = blockIdx.x * blockDim.x + threadIdx.x;
    if (i < NNODES) {
        int o = g_offloc[i] + g_bpre[i >> 10];
        g_off[i] = o;
        g_cur[i] = o;
    }
    if (i == 0) g_off[NNODES] = NEDGES;
}

// ---------------- bucket: sort edges by destination --------------------------
__global__ void k_bucket(const float* __restrict__ ew) {
    int e = blockIdx.x * blockDim.x + threadIdx.x;
    if (e >= NEDGES) return;
    int2 rc = g_rc[e];
    float w = 1.f / (1.f + __expf(-ew[e]));
    float ne = g_dis[rc.x] * w * g_dis[rc.y];
    int pos = atomicAdd(&g_cur[rc.y], 1);
    g_ed[pos] = make_uint2((unsigned)rc.x, __float_as_uint(ne));
}

// ---------------- GEMM: xp = x @ (W/sigma)  (packed f32x2) -------------------
__global__ __launch_bounds__(256, 2)
void k_gemm(const float* __restrict__ x, const float* __restrict__ W) {
    __shared__ __align__(16) float Ws[FIN * FOUT];  // 32 KB
    float is = g_inv_sigma;
    for (int i = threadIdx.x; i < FIN * FOUT; i += 256)
        Ws[i] = W[i] * is;
    __syncthreads();

    int row = blockIdx.x * 256 + threadIdx.x;
    if (row >= NNODES) return;

    ull acc[32];
    #pragma unroll
    for (int j = 0; j < 32; j++) acc[j] = 0ull;

    const float4* xr = (const float4*)(x + (size_t)row * FIN);
    for (int k4 = 0; k4 < FIN / 4; ++k4) {
        float4 xv = xr[k4];
        #pragma unroll
        for (int kk = 0; kk < 4; kk++) {
            float xk = (kk == 0) ? xv.x : (kk == 1) ? xv.y : (kk == 2) ? xv.z : xv.w;
            ull xx = dup2(xk);
            const ulonglong2* wr = (const ulonglong2*)&Ws[(k4 * 4 + kk) * FOUT];
            #pragma unroll
            for (int j = 0; j < 16; j++) {
                ulonglong2 w = wr[j];
                acc[2 * j]     = fma2(xx, w.x, acc[2 * j]);
                acc[2 * j + 1] = fma2(xx, w.y, acc[2 * j + 1]);
            }
        }
    }

    ulonglong2* xpr = (ulonglong2*)&g_xp[(size_t)row * FOUT];
    #pragma unroll
    for (int j = 0; j < 16; j++) {
        ulonglong2 t; t.x = acc[2 * j]; t.y = acc[2 * j + 1];
        xpr[j] = t;
    }
}

// ---------------- gather: warp per node, no fp atomics -----------------------
__global__ __launch_bounds__(256)
void k_gather(const float* __restrict__ bias, float* __restrict__ out) {
    int wid = threadIdx.x >> 5, lane = threadIdx.x & 31;
    int node = blockIdx.x * 8 + wid;
    if (node >= NNODES) return;

    int beg = g_off[node], end = g_off[node + 1];
    float ax = 0.f, ay = 0.f;
    for (int p = beg; p < end; ++p) {
        uint2 ed = g_ed[p];                         // broadcast load
        float ne = __uint_as_float(ed.y);
        float2 v = ((const float2*)(g_xp + (size_t)ed.x * FOUT))[lane];
        ax = fmaf(v.x, ne, ax);
        ay = fmaf(v.y, ne, ay);
    }
    float2 s = ((const float2*)(g_xp + (size_t)node * FOUT))[lane];
    float id = g_invdeg[node];
    float2 b = ((const float2*)bias)[lane];
    float2 o;
    o.x = fmaf(s.x, id, b.x) + ax;
    o.y = fmaf(s.y, id, b.y) + ay;
    ((float2*)(out + (size_t)node * FOUT))[lane] = o;
}

// ---------------- launcher ----------------------------------------------------
extern "C" void kernel_launch(void* const* d_in, const int* in_sizes, int n_in,
                              void* d_out, int out_size) {
    const float* x    = (const float*)d_in[0];
    const void*  ei   = d_in[1];
    const float* W    = (const float*)d_in[2];
    const float* bias = (const float*)d_in[3];
    const float* ew   = (const float*)d_in[4];
    const float* u    = (const float*)d_in[5];
    float* out = (float*)d_out;

    k_prep<<<1, 128>>>(ei, W, u);
    k_zero<<<(NNODES + 255) / 256, 256>>>();
    k_deg<<<(NEDGES + 255) / 256, 256>>>(ei, ew);
    k_dis<<<(NNODES + 255) / 256, 256>>>();
    k_scan_blk<<<NBLK, 1024>>>();
    k_scan_top<<<1, 128>>>();
    k_scan_add<<<(NNODES + 255) / 256, 256>>>();
    k_bucket<<<(NEDGES + 255) / 256, 256>>>(ew);
    k_gemm<<<(NNODES + 255) / 256, 256>>>(x, W);
    k_gather<<<(NNODES + 7) / 8, 256>>>(bias, out);
}